// round 6
// baseline (speedup 1.0000x reference)
#include <cuda_runtime.h>
#include <cuda_fp16.h>

// Inputs (harness upcasts f16 arrays to f32):
//   x:      [N=16384, DIM=4096] f32 (f16-valued)
//   pairs:  [KROT=8, DIM]       int32 (same local pattern tiled per 128-group)
//   theta:  [KROT, DIM/2]       f32 (f16-valued)
//   scales: [1, DIM]            f32 (f16-valued)
//   out:    [N, DIM]            f32
// Reference rounds to f16 after EVERY op -> *_rn intrinsics (no HFMA2 contraction).
// Bit-exact vs reference (rel_err = 0.0 in R3/R4/R5).
#define DIMV   4096
#define KROT   8
#define NPAIR  2048
#define GRP    128
#define NGRP   32
#define ILG    64
#define ROWS   8
#define TPB    512
#define NTILES 2048       // 16384 / ROWS
#define GRIDX  152        // GB300: 152 SMs, 1 persistent 128KB block each

// g_cs layout: [k][il*32 + g] -> lanes (=group) read one coalesced 128B line.
__device__ __half2  g_cs[KROT * NPAIR];
__device__ unsigned g_ab[KROT * ILG];

struct __align__(16) H8 { __half2 r01, r23, r45, r67; };  // 8 rows of one channel

// slot(c,g) = c*32 + (g ^ (c>>2)): conflict-free for both access phases.
__device__ __forceinline__ int slot(int c, int g) {
    return (c << 5) + (g ^ (c >> 2));
}

__global__ void prep_kernel(const float* __restrict__ theta,
                            const int* __restrict__ pairs) {
    int idx = blockIdx.x * blockDim.x + threadIdx.x;
    if (idx < KROT * NPAIR) {
        int k  = idx >> 11;
        int i  = idx & (NPAIR - 1);
        int g  = i >> 6;
        int il = i & (ILG - 1);
        float t = theta[idx];
        __half c = __float2half(cosf(t));
        __half s = __float2half(sinf(t));
        g_cs[(k << 11) + (il << 5) + g] = __halves2half2(c, s);
    }
    if (idx < KROT * ILG) {
        int k  = idx >> 6;
        int il = idx & (ILG - 1);
        int a = pairs[k * DIMV + 2 * il];
        int b = pairs[k * DIMV + 2 * il + 1];
        g_ab[idx] = (unsigned)(a | (b << 8));
    }
}

// Convert one staged quad (4 channels x 8 rows held as float4 v[8]) into smem.
__device__ __forceinline__ void sts_quad(H8* S, const float4* v, int c0, int gg) {
    const float* f = reinterpret_cast<const float*>(v);   // f[r*4 + j]
    #pragma unroll
    for (int j = 0; j < 4; j++) {
        H8 w;
        w.r01 = __floats2half2_rn(f[0*4+j], f[1*4+j]);    // exact: inputs f16-valued
        w.r23 = __floats2half2_rn(f[2*4+j], f[3*4+j]);
        w.r45 = __floats2half2_rn(f[4*4+j], f[5*4+j]);
        w.r67 = __floats2half2_rn(f[6*4+j], f[7*4+j]);
        S[slot(c0 + j, gg)] = w;                          // STS.128, conflict-free
    }
}

__global__ void __launch_bounds__(TPB)
rot_kernel(const float* __restrict__ x,
           const float* __restrict__ scales,
           float* __restrict__ out) {
    extern __shared__ H8 sm[];             // 2 x 4096 x 16B = 128KB (W + S)
    const int tid = threadIdx.x;
    const int g   = tid & 31;              // lane = group in rotation phase
    const int ilb = tid >> 5;              // warp id = il base

    int t = blockIdx.x;
    int cur = 0;

    // ---- Prologue: stage first tile into buffer 0 ----
    {
        const float* xb = x + (size_t)t * (ROWS * DIMV);
        #pragma unroll
        for (int qi = 0; qi < 2; qi++) {
            int q = tid + qi * TPB;
            int gg = q >> 5, c0 = (q & 31) * 4;
            const float* p = xb + gg * GRP + c0;
            float4 v[8];
            #pragma unroll
            for (int r = 0; r < 8; r++) v[r] = *(const float4*)(p + r * DIMV);
            sts_quad(sm, v, c0, gg);
        }
    }
    __syncthreads();

    // ---- Persistent tile loop: rotate W while prefetching next tile into S ----
    while (true) {
        const int  nxt      = t + GRIDX;
        const bool has_next = (nxt < NTILES);
        H8* W = sm + cur * DIMV;
        H8* S = sm + (cur ^ 1) * DIMV;
        const float* nb = x + (size_t)nxt * (ROWS * DIMV);

        float4 v0[8], v1[8];
        const int gg0 = tid >> 5,         c00 = (tid & 31) * 4;          // quad 0
        const int gg1 = (tid + TPB) >> 5, c01 = ((tid + TPB) & 31) * 4;  // quad 1

        #pragma unroll
        for (int k = 0; k < KROT; k++) {
            // Prefetch LDG bursts early in the layer (latency hidden by compute).
            if (k == 0 && has_next) {
                const float* p = nb + gg0 * GRP + c00;
                #pragma unroll
                for (int r = 0; r < 8; r++) v0[r] = *(const float4*)(p + r * DIMV);
            }
            if (k == 3 && has_next) {
                const float* p = nb + gg1 * GRP + c01;
                #pragma unroll
                for (int r = 0; r < 8; r++) v1[r] = *(const float4*)(p + r * DIMV);
            }

            // Rotation layer k: 16 warps span il, lanes span g; 4 pairs/thread.
            #pragma unroll
            for (int s4 = 0; s4 < 4; s4++) {
                int il = ilb + (s4 << 4);
                unsigned ab = g_ab[(k << 6) + il];             // warp-uniform
                __half2 cs = g_cs[(k << 11) + (il << 5) + g];  // coalesced; L1-warm
                int a = ab & 255, b = (ab >> 8) & 255;
                int wa = slot(a, g), wb = slot(b, g);
                H8 ua = W[wa], ub = W[wb];                     // LDS.128 x2
                __half2 hc = __half2half2(__low2half(cs));
                __half2 hs = __half2half2(__high2half(cs));
                H8 ra, rb;
                // Per-op f16 rounding, contraction forbidden, reference order.
                ra.r01 = __hsub2_rn(__hmul2_rn(hc, ua.r01), __hmul2_rn(hs, ub.r01));
                rb.r01 = __hadd2_rn(__hmul2_rn(hs, ua.r01), __hmul2_rn(hc, ub.r01));
                ra.r23 = __hsub2_rn(__hmul2_rn(hc, ua.r23), __hmul2_rn(hs, ub.r23));
                rb.r23 = __hadd2_rn(__hmul2_rn(hs, ua.r23), __hmul2_rn(hc, ub.r23));
                ra.r45 = __hsub2_rn(__hmul2_rn(hc, ua.r45), __hmul2_rn(hs, ub.r45));
                rb.r45 = __hadd2_rn(__hmul2_rn(hs, ua.r45), __hmul2_rn(hc, ub.r45));
                ra.r67 = __hsub2_rn(__hmul2_rn(hc, ua.r67), __hmul2_rn(hs, ub.r67));
                rb.r67 = __hadd2_rn(__hmul2_rn(hs, ua.r67), __hmul2_rn(hc, ub.r67));
                W[wa] = ra; W[wb] = rb;                        // STS.128 x2
            }

            // Drain staged quads into S mid-pipeline (S disjoint from W).
            if (k == 2 && has_next) sts_quad(S, v0, c00, gg0);
            if (k == 5 && has_next) sts_quad(S, v1, c01, gg1);

            __syncthreads();   // pairs disjoint within a layer; sync between layers
        }

        // ---- Store W with channel scaling (coalesced float4 per row) ----
        {
            float* ob = out + (size_t)t * (ROWS * DIMV);
            #pragma unroll
            for (int qi = 0; qi < 2; qi++) {
                int q = tid + qi * TPB;
                int gg = q >> 5, c0 = (q & 31) * 4;
                int d = gg * GRP + c0;
                float4 sc4 = *(const float4*)(scales + d);
                const float* ps = &sc4.x;
                float o[8][4];
                #pragma unroll
                for (int j = 0; j < 4; j++) {
                    H8 w = W[slot(c0 + j, gg)];                  // LDS.128
                    __half2 sc2 = __half2half2(__float2half(ps[j]));  // exact
                    __half2 p01 = __hmul2_rn(w.r01, sc2);
                    __half2 p23 = __hmul2_rn(w.r23, sc2);
                    __half2 p45 = __hmul2_rn(w.r45, sc2);
                    __half2 p67 = __hmul2_rn(w.r67, sc2);
                    o[0][j] = __half2float(__low2half (p01));
                    o[1][j] = __half2float(__high2half(p01));
                    o[2][j] = __half2float(__low2half (p23));
                    o[3][j] = __half2float(__high2half(p23));
                    o[4][j] = __half2float(__low2half (p45));
                    o[5][j] = __half2float(__high2half(p45));
                    o[6][j] = __half2float(__low2half (p67));
                    o[7][j] = __half2float(__high2half(p67));
                }
                float* qp = ob + d;
                #pragma unroll
                for (int r = 0; r < ROWS; r++)
                    *(float4*)(qp + r * DIMV) =
                        make_float4(o[r][0], o[r][1], o[r][2], o[r][3]);
            }
        }

        if (!has_next) break;
        __syncthreads();       // all reads of W done before it becomes next S
        cur ^= 1;
        t = nxt;
    }
}

extern "C" void kernel_launch(void* const* d_in, const int* in_sizes, int n_in,
                              void* d_out, int out_size) {
    const float* x      = (const float*)d_in[0];
    const int*   pairs  = (const int*)d_in[1];
    const float* theta  = (const float*)d_in[2];
    const float* scales = (const float*)d_in[3];
    (void)n_in; (void)in_sizes; (void)out_size;

    const int smem = 2 * DIMV * (int)sizeof(H8);   // 128KB dynamic
    cudaFuncSetAttribute(rot_kernel, cudaFuncAttributeMaxDynamicSharedMemorySize, smem);

    prep_kernel<<<(KROT * NPAIR + 255) / 256, 256>>>(theta, pairs);
    rot_kernel<<<GRIDX, TPB, smem>>>(x, scales, (float*)d_out);
}